// round 1
// baseline (speedup 1.0000x reference)
#include <cuda_runtime.h>

#define BB 8
#define NN 2048
#define FF 256
#define ALPHA 0.2f

// Scratch (allocation-free rule: __device__ globals)
__device__ float g_Wh[BB * NN * FF];   // 16 MB
__device__ float g_WT[FF * FF];        // W transposed: [k][o]
__device__ float g_s1[BB * NN];
__device__ float g_s2[BB * NN];

// ---------------------------------------------------------------------------
// K0: transpose W [F_OUT, F_IN] -> g_WT [F_IN, F_OUT]   (tiny)
// ---------------------------------------------------------------------------
__global__ void transpose_W(const float* __restrict__ W) {
    __shared__ float tile[32][33];
    int k0 = blockIdx.x * 32;
    int o0 = blockIdx.y * 32;
    int lx = threadIdx.x & 31;      // inner (k on load)
    int ly = threadIdx.x >> 5;      // 0..7
#pragma unroll
    for (int s = 0; s < 32; s += 8)
        tile[ly + s][lx] = W[(o0 + ly + s) * FF + (k0 + lx)];
    __syncthreads();
#pragma unroll
    for (int s = 0; s < 32; s += 8)
        g_WT[(k0 + ly + s) * FF + (o0 + lx)] = tile[lx][ly + s];
}

// ---------------------------------------------------------------------------
// K1: Wh[row][o] = sum_k h[row][k] * W[o][k], rows = B*N flattened.
// Block: 64 rows x 256 outs, 256 threads, 8x8 micro-tile, K tiled by 32.
// ---------------------------------------------------------------------------
__global__ __launch_bounds__(256) void gemm_Wh(const float* __restrict__ h) {
    __shared__ float hs[64][32];     // [row][k]
    __shared__ float ws[32][256];    // [k][o]
    const int row0 = blockIdx.x * 64;
    const int t  = threadIdx.x;
    const int ty = t >> 5, tx = t & 31;
    const int r0 = ty * 8, o0 = tx * 8;

    float acc[8][8];
#pragma unroll
    for (int i = 0; i < 8; i++)
#pragma unroll
        for (int j = 0; j < 8; j++) acc[i][j] = 0.0f;

    for (int k0 = 0; k0 < FF; k0 += 32) {
        // load hs: 512 float4, 2 per thread.  v: row = v>>3, c = v&7
        {
            float4* dst = (float4*)hs;
#pragma unroll
            for (int s = 0; s < 2; s++) {
                int v = t + 256 * s;
                int row = v >> 3, c = v & 7;
                dst[v] = ((const float4*)(h + (size_t)(row0 + row) * FF + k0))[c];
            }
        }
        // load ws: 2048 float4, 8 per thread.  v: kk = v>>6, c = v&63
        {
            float4* dst = (float4*)ws;
#pragma unroll
            for (int s = 0; s < 8; s++) {
                int v = t + 256 * s;
                int kk = v >> 6, c = v & 63;
                dst[v] = ((const float4*)(g_WT + (size_t)(k0 + kk) * FF))[c];
            }
        }
        __syncthreads();

#pragma unroll 8
        for (int kk = 0; kk < 32; kk++) {
            float av[8];
#pragma unroll
            for (int i = 0; i < 8; i++) av[i] = hs[r0 + i][kk];  // warp-uniform (broadcast)
            float4 w0 = *(const float4*)&ws[kk][o0];
            float4 w1 = *(const float4*)&ws[kk][o0 + 4];
            float bv[8] = {w0.x, w0.y, w0.z, w0.w, w1.x, w1.y, w1.z, w1.w};
#pragma unroll
            for (int i = 0; i < 8; i++)
#pragma unroll
                for (int j = 0; j < 8; j++) acc[i][j] += av[i] * bv[j];
        }
        __syncthreads();
    }

#pragma unroll
    for (int i = 0; i < 8; i++) {
        float* dst = g_Wh + (size_t)(row0 + r0 + i) * FF + o0;
        *(float4*)(dst)     = make_float4(acc[i][0], acc[i][1], acc[i][2], acc[i][3]);
        *(float4*)(dst + 4) = make_float4(acc[i][4], acc[i][5], acc[i][6], acc[i][7]);
    }
}

// ---------------------------------------------------------------------------
// K2: s1[row] = Wh[row] . a1, s2[row] = Wh[row] . a2.  One warp per row.
// ---------------------------------------------------------------------------
__global__ void compute_s(const float* __restrict__ a) {
    int gw = (blockIdx.x * blockDim.x + threadIdx.x) >> 5;   // row
    int lane = threadIdx.x & 31;
    if (gw >= BB * NN) return;
    const float4* whr = (const float4*)(g_Wh + (size_t)gw * FF);
    const float4* a1v = (const float4*)a;          // a[0,  0:256)
    const float4* a2v = ((const float4*)a) + 64;   // a[0,256:512)
    float s1 = 0.0f, s2 = 0.0f;
#pragma unroll
    for (int s = 0; s < 2; s++) {
        float4 v  = whr[lane * 2 + s];
        float4 c1 = a1v[lane * 2 + s];
        float4 c2 = a2v[lane * 2 + s];
        s1 += v.x * c1.x + v.y * c1.y + v.z * c1.z + v.w * c1.w;
        s2 += v.x * c2.x + v.y * c2.y + v.z * c2.z + v.w * c2.w;
    }
#pragma unroll
    for (int off = 16; off; off >>= 1) {
        s1 += __shfl_xor_sync(0xffffffffu, s1, off);
        s2 += __shfl_xor_sync(0xffffffffu, s2, off);
    }
    if (lane == 0) { g_s1[gw] = s1; g_s2[gw] = s2; }
}

// ---------------------------------------------------------------------------
// K3: attention. Block = 64 rows x all 256 features of one batch.
// j-tiles of 32. No max-subtraction needed (|logit| <~ 10, exp safe in fp32).
// Stage A: p-tile (masked exp).  Stage B: 8x8-register PV microkernel.
// ---------------------------------------------------------------------------
__global__ __launch_bounds__(256, 2) void attn(const int* __restrict__ adj,
                                               float* __restrict__ out) {
    __shared__ float whs[32][256];   // [j][f]
    __shared__ float ps[64][36];     // [i][j] (+pad)
    __shared__ float s2s[32];
    __shared__ float ls[64];

    const int b  = blockIdx.y;
    const int i0 = blockIdx.x * 64;
    const int t  = threadIdx.x;
    const int ty = t >> 5, tx = t & 31;
    const int r0 = ty * 8, f0 = tx * 8;

    // stage-A mapping: 4 threads per row, 8 j's each
    const int arow = t >> 2;
    const int ajl  = (t & 3) * 8;
    const float s1v = g_s1[(size_t)b * NN + i0 + arow];
    const int* adjrow = adj + ((size_t)b * NN + i0 + arow) * NN;

    if (t < 64) ls[t] = 0.0f;

    float acc[8][8];
#pragma unroll
    for (int i = 0; i < 8; i++)
#pragma unroll
        for (int j = 0; j < 8; j++) acc[i][j] = 0.0f;

    for (int j0 = 0; j0 < NN; j0 += 32) {
        __syncthreads();  // previous stage B done before overwriting whs/ps/s2s

        if (t < 32) s2s[t] = g_s2[(size_t)b * NN + j0 + t];
        {
            const float4* src = (const float4*)(g_Wh + ((size_t)b * NN + j0) * FF);
            float4* dst = (float4*)whs;   // 2048 float4, 8 per thread
#pragma unroll
            for (int s = 0; s < 8; s++) dst[t + 256 * s] = src[t + 256 * s];
        }
        __syncthreads();  // s2s/whs visible

        // ---- stage A: masked p-tile ----
        {
            int4 av0 = *(const int4*)(adjrow + j0 + ajl);
            int4 av1 = *(const int4*)(adjrow + j0 + ajl + 4);
            int ad[8] = {av0.x, av0.y, av0.z, av0.w, av1.x, av1.y, av1.z, av1.w};
            float pv[8];
            float psum = 0.0f;
#pragma unroll
            for (int s = 0; s < 8; s++) {
                float x = s1v + s2s[ajl + s];
                float e = (x > 0.0f) ? x : ALPHA * x;
                float p = ad[s] ? __expf(e) : 0.0f;
                pv[s] = p;
                psum += p;
            }
            *(float4*)&ps[arow][ajl]     = make_float4(pv[0], pv[1], pv[2], pv[3]);
            *(float4*)&ps[arow][ajl + 4] = make_float4(pv[4], pv[5], pv[6], pv[7]);
            psum += __shfl_xor_sync(0xffffffffu, psum, 1);
            psum += __shfl_xor_sync(0xffffffffu, psum, 2);
            if ((t & 3) == 0) ls[arow] += psum;   // one writer per row
        }
        __syncthreads();  // ps ready

        // ---- stage B: acc += p * Wh ----
#pragma unroll 4
        for (int jj = 0; jj < 32; jj++) {
            float4 w0 = *(const float4*)&whs[jj][f0];
            float4 w1 = *(const float4*)&whs[jj][f0 + 4];
            float wv[8] = {w0.x, w0.y, w0.z, w0.w, w1.x, w1.y, w1.z, w1.w};
#pragma unroll
            for (int i = 0; i < 8; i++) {
                float p = ps[r0 + i][jj];   // warp-uniform -> broadcast
#pragma unroll
                for (int j = 0; j < 8; j++) acc[i][j] += p * wv[j];
            }
        }
    }

    // epilogue: out = acc / l  (ls last written before the final pre-stage-B sync)
#pragma unroll
    for (int i = 0; i < 8; i++) {
        float inv = 1.0f / ls[r0 + i];
        float* dst = out + ((size_t)b * NN + i0 + r0 + i) * FF + f0;
        *(float4*)(dst)     = make_float4(acc[i][0] * inv, acc[i][1] * inv,
                                          acc[i][2] * inv, acc[i][3] * inv);
        *(float4*)(dst + 4) = make_float4(acc[i][4] * inv, acc[i][5] * inv,
                                          acc[i][6] * inv, acc[i][7] * inv);
    }
}

// ---------------------------------------------------------------------------
extern "C" void kernel_launch(void* const* d_in, const int* in_sizes, int n_in,
                              void* d_out, int out_size) {
    const float* h   = (const float*)d_in[0];
    const int*   adj = (const int*)d_in[1];
    const float* W   = (const float*)d_in[2];
    const float* a   = (const float*)d_in[3];
    float* out = (float*)d_out;

    transpose_W<<<dim3(FF / 32, FF / 32), 256>>>(W);
    gemm_Wh<<<(BB * NN) / 64, 256>>>(h);
    compute_s<<<(BB * NN) / 8, 256>>>(a);
    attn<<<dim3(NN / 64, BB), 256>>>(adj, out);
}